// round 10
// baseline (speedup 1.0000x reference)
#include <cuda_runtime.h>
#include <math.h>

// Problem constants (fixed by setup_inputs)
#define NB    16
#define NH    76
#define NW    76
#define NCH   32          // 19 + NC
#define HW    (NH*NW)     // 5776
#define NL    21          // 2*NK + 3
#define TX    16          // tile width (cells)
#define TYC   16          // tile height (cells)
#define TPB   128         // threads; each owns 2 cells: (i,j) and (i,j+8)
#define GXN   5
#define GYN   5
#define NBLK  (GXN * GYN * NB)           // 400
#define GSTR  20                         // s_gt row stride (floats)
#define KSTR  56                         // s_key target-dim padding

#define FULLM 0xffffffffu

__device__ float        g_partials[NBLK];
__device__ unsigned int g_count;   // zero at load; last block subtracts NBLK (replay-safe)

__device__ __forceinline__ float fsigmoid(float x) {
    return 1.0f / (1.0f + __expf(-x));
}
// order-preserving float -> uint key (monotone total order)
__device__ __forceinline__ unsigned f2o(float f) {
    unsigned u = __float_as_uint(f);
    unsigned s = (unsigned)(((int)u) >> 31);
    return u ^ (s | 0x80000000u);
}

__global__ void __launch_bounds__(TPB)
loss_kernel(const float* __restrict__ out,
            const float* __restrict__ dst,
            const float* __restrict__ tgt,
            float* __restrict__ res)
{
    __shared__ float    s_raw[50 * NL];     // staged target rows (coalesced load)
    __shared__ float    s_gt[50 * GSTR];    // corners in pixels (rare exact path)
    __shared__ uint4    s_key[9][KSTR];     // expanded box keys, corner-major
    __shared__ unsigned s_mask[2];
    __shared__ int      s_map[TX * TYC];    // packed (t+1)<<8 | cls per local cell
    __shared__ float    s_red[TPB / 32];
    __shared__ bool     s_last;

    const int b    = blockIdx.z;
    const int tid  = threadIdx.x;
    const int lane = tid & 31;
    const float* T = tgt + (size_t)b * (50 * NL);

    s_map[tid]       = 0;
    s_map[tid + TPB] = 0;

    // Phase 0: coalesced stage of all target data
    #pragma unroll
    for (int idx = tid; idx < 50 * NL; idx += TPB) s_raw[idx] = T[idx];
    __syncthreads();

    // Phase 1: 450 corner-key tasks spread over all threads
    for (int task = tid; task < 450; task += TPB) {
        int t = task / 9, k = task - 9 * t;
        float gx = s_raw[t * NL + 1 + 2 * k] * 640.0f;
        float gy = s_raw[t * NL + 2 + 2 * k] * 480.0f;
        s_gt[t * GSTR + 2 * k    ] = gx;
        s_gt[t * GSTR + 2 * k + 1] = gy;
        s_key[k][t] = make_uint4(f2o(gx - 80.5f), f2o(gx + 80.5f),
                                 f2o(gy - 80.5f), f2o(gy + 80.5f));
    }
    if (tid < 64) {   // warps 0,1 full — ballot legal
        float xv = (tid < 50) ? s_raw[tid * NL + 1] : 0.0f;
        unsigned m = __ballot_sync(FULLM, xv != 0.0f);
        if (lane == 0) s_mask[tid >> 5] = m;
    }
    __syncthreads();

    // nv = leading-valid prefix length (cumprod semantics)
    const unsigned m0v = s_mask[0], m1v = s_mask[1];
    int nv;
    if (~m0v)      nv = __ffs(~m0v) - 1;
    else if (~m1v) nv = 32 + __ffs(~m1v) - 1;
    else           nv = 64;
    if (nv > 50) nv = 50;

    // Phase 2: targeted-cell map (last valid t wins == max t wins)
    const int bx0 = blockIdx.x * TX, by0 = blockIdx.y * TYC;
    if (tid < nv) {
        int gi = (int)(s_raw[tid * NL + 1] * (float)NW);
        int gj = (int)(s_raw[tid * NL + 2] * (float)NH);
        int li = gi - bx0, lj = gj - by0;
        if (li >= 0 && li < TX && lj >= 0 && lj < TYC)
            atomicMax(&s_map[lj * TX + li], ((tid + 1) << 8) | (int)s_raw[tid * NL]);
    }
    __syncthreads();

    // Per-thread cells A=(i,j) and B=(i,j+8); edge threads clamp to cell 75 (box stays tight)
    const int  i   = bx0 + (tid & (TX - 1));
    const int  jA  = by0 + (tid >> 4);
    const int  jB  = jA + 8;
    const int  iC  = i  < NW ? i  : NW - 1;
    const int  jAC = jA < NH ? jA : NH - 1;
    const int  jBC = jB < NH ? jB : NH - 1;
    const bool inbA = (i < NW) && (jA < NH);
    const bool inbB = (i < NW) && (jB < NH);
    const float* OA = out + (size_t)b * NCH * HW + jAC * NW + iC;
    const float* OB = out + (size_t)b * NCH * HW + jBC * NW + iC;
    const float* DA = dst + (size_t)b * NCH * HW + jAC * NW + iC;
    const float* DB = dst + (size_t)b * NCH * HW + jBC * NW + iC;

    const float sX  = 640.0f / (float)NW;
    const float sY  = 480.0f / (float)NH;
    const float fiC = (float)iC, fjA = (float)jAC, fjB = (float)jBC;

    // Phase 3: per-corner keys for both cells (pairwise min/max), then batched REDUX
    unsigned kxmn[9], kxmx[9], kymn[9], kymx[9];
    #pragma unroll
    for (int k = 0; k < 9; k++) {
        float axA = OA[(size_t)(2 * k    ) * HW];
        float ayA = OA[(size_t)(2 * k + 1) * HW];
        float axB = OB[(size_t)(2 * k    ) * HW];
        float ayB = OB[(size_t)(2 * k + 1) * HW];
        if (k == 0) { axA = fsigmoid(axA); ayA = fsigmoid(ayA);
                      axB = fsigmoid(axB); ayB = fsigmoid(ayB); }
        unsigned ka = f2o((axA + fiC) * sX), kb = f2o((axB + fiC) * sX);
        unsigned la = f2o((ayA + fjA) * sY), lb = f2o((ayB + fjB) * sY);
        kxmn[k] = ka < kb ? ka : kb;  kxmx[k] = ka > kb ? ka : kb;
        kymn[k] = la < lb ? la : lb;  kymx[k] = la > lb ? la : lb;
    }
    unsigned mnx[9], mxx[9], mny[9], mxy[9];
    #pragma unroll
    for (int k = 0; k < 9; k++) {
        mnx[k] = __reduce_min_sync(FULLM, kxmn[k]);
        mxx[k] = __reduce_max_sync(FULLM, kxmx[k]);
        mny[k] = __reduce_min_sync(FULLM, kymn[k]);
        mxy[k] = __reduce_max_sync(FULLM, kymx[k]);
    }

    // Phase 4: per-lane target cull (two halves), survivor iff >=6 corners overlap
    int cnt0 = 0, cnt1 = 0;
    const bool nvgt32 = (nv > 32);
    #pragma unroll
    for (int k = 0; k < 9; k++) {
        uint4 tk = s_key[k][lane];
        cnt0 += (mnx[k] <= tk.y && mxx[k] >= tk.x &&
                 mny[k] <= tk.w && mxy[k] >= tk.z) ? 1 : 0;
    }
    if (nvgt32 && lane + 32 < 50) {
        #pragma unroll
        for (int k = 0; k < 9; k++) {
            uint4 tk = s_key[k][lane + 32];
            cnt1 += (mnx[k] <= tk.y && mxx[k] >= tk.x &&
                     mny[k] <= tk.w && mxy[k] >= tk.z) ? 1 : 0;
        }
    }
    unsigned sm0 = __ballot_sync(FULLM, (lane < nv) && cnt0 >= 6);
    unsigned sm1 = nvgt32 ? __ballot_sync(FULLM, (lane + 32 < nv) && cnt1 >= 6) : 0u;

    // Phase 5: exact evaluation for rare survivors (warp-uniform branch)
    bool silA = false, silB = false;
    unsigned long long smask = (((unsigned long long)sm1) << 32) | sm0;
    if (smask) {
        do {
            int t = __ffsll(smask) - 1;
            smask &= smask - 1;
            const float* gp = s_gt + t * GSTR;
            float d2A[9], d2B[9];
            int cA = 0, cB = 0;
            #pragma unroll
            for (int k = 0; k < 9; k++) {
                float2 gv = *reinterpret_cast<const float2*>(gp + 2 * k);
                float axA = OA[(size_t)(2 * k    ) * HW];
                float ayA = OA[(size_t)(2 * k + 1) * HW];
                float axB = OB[(size_t)(2 * k    ) * HW];
                float ayB = OB[(size_t)(2 * k + 1) * HW];
                if (k == 0) { axA = fsigmoid(axA); ayA = fsigmoid(ayA);
                              axB = fsigmoid(axB); ayB = fsigmoid(ayB); }
                float dxA = gv.x - (axA + fiC) * sX;
                float dyA = gv.y - (ayA + fjA) * sY;
                float dxB = gv.x - (axB + fiC) * sX;
                float dyB = gv.y - (ayB + fjB) * sY;
                d2A[k] = fmaf(dxA, dxA, dyA * dyA);
                d2B[k] = fmaf(dxB, dxB, dyB * dyB);
                cA += (d2A[k] < 6400.0f) ? 1 : 0;
                cB += (d2B[k] < 6400.0f) ? 1 : 0;
            }
            if (cA >= 6) {
                float s = 0.0f;
                #pragma unroll
                for (int k = 0; k < 9; k++) {
                    float dist = sqrtf(d2A[k]);
                    float c = (expf(2.0f * (1.0f - dist * (1.0f / 80.0f))) - 1.0f)
                              * (1.0f / 6.3890560989306495f);
                    s += (dist < 80.0f) ? c : 0.0f;
                }
                if (s * (1.0f / 9.0f) > 0.6f) silA = true;
            }
            if (cB >= 6) {
                float s = 0.0f;
                #pragma unroll
                for (int k = 0; k < 9; k++) {
                    float dist = sqrtf(d2B[k]);
                    float c = (expf(2.0f * (1.0f - dist * (1.0f / 80.0f))) - 1.0f)
                              * (1.0f / 6.3890560989306495f);
                    s += (dist < 80.0f) ? c : 0.0f;
                }
                if (s * (1.0f / 9.0f) > 0.6f) silB = true;
            }
        } while (smask);
    }

    // Phase 6: losses for both cells
    float loss = 0.0f;
    #pragma unroll
    for (int half = 0; half < 2; half++) {
        const bool  inb = half ? inbB : inbA;
        if (!inb) continue;
        const float* O  = half ? OB : OA;
        const float* D  = half ? DB : DA;
        const bool  sil = half ? silB : silA;
        const int   mpk = s_map[tid + half * TPB];
        const bool  targeted = (mpk != 0);
        const int   tc       = mpk & 0xff;

        const float conf  = fsigmoid(O[(size_t)18 * HW]);
        const float tconf = fsigmoid(D[(size_t)18 * HW]);
        const float cm  = targeted ? 5.0f : (sil ? 0.0f : 1.0f);
        const float dcf = conf - tconf;
        loss += 0.5f * dcf * dcf * cm;

        if (targeted) {   // rare (~1 cell per target)
            float lc = 0.0f;
            {
                float d0 = fsigmoid(O[0])  - fsigmoid(D[0]);
                float d1 = fsigmoid(O[HW]) - fsigmoid(D[HW]);
                lc += d0 * d0 + d1 * d1;
            }
            #pragma unroll
            for (int c = 2; c < 18; c++) {
                float dd = O[(size_t)c * HW] - D[(size_t)c * HW];
                lc += dd * dd;
            }
            loss += 0.5f * lc;

            float l[13];
            #pragma unroll
            for (int c = 0; c < 13; c++) l[c] = O[(size_t)(19 + c) * HW];
            float mx = l[0];
            #pragma unroll
            for (int c = 1; c < 13; c++) mx = fmaxf(mx, l[c]);
            float se = 0.0f;
            #pragma unroll
            for (int c = 0; c < 13; c++) se += expf(l[c] - mx);
            loss += (mx + logf(se)) - l[tc];
        }
    }

    // Deterministic intra-block reduction (4 warps)
    #pragma unroll
    for (int off = 16; off; off >>= 1)
        loss += __shfl_down_sync(FULLM, loss, off);
    if (lane == 0) s_red[tid >> 5] = loss;
    __syncthreads();
    if (tid == 0) {
        float v = s_red[0] + s_red[1] + s_red[2] + s_red[3];
        g_partials[(blockIdx.z * GYN + blockIdx.y) * GXN + blockIdx.x] = v;
        __threadfence();
        unsigned old = atomicAdd(&g_count, 1u);
        s_last = (old == (unsigned)(NBLK - 1));
    }
    __syncthreads();

    // Last block: fixed-order final reduction (deterministic)
    if (s_last && tid < 32) {
        float s = 0.0f;
        for (int idx = tid; idx < NBLK; idx += 32)
            s += g_partials[idx];
        #pragma unroll
        for (int off = 16; off; off >>= 1)
            s += __shfl_down_sync(FULLM, s, off);
        if (tid == 0) {
            res[0] = s;
            atomicSub(&g_count, (unsigned)NBLK);   // replay-safe reset
        }
    }
}

extern "C" void kernel_launch(void* const* d_in, const int* in_sizes, int n_in,
                              void* d_out, int out_size)
{
    const float* out = (const float*)d_in[0];
    const float* dst = (const float*)d_in[1];
    const float* tgt = (const float*)d_in[2];
    (void)in_sizes; (void)n_in; (void)out_size;

    dim3 grid(GXN, GYN, NB);
    loss_kernel<<<grid, TPB>>>(out, dst, tgt, (float*)d_out);
}

// round 11
// speedup vs baseline: 1.1555x; 1.1555x over previous
#include <cuda_runtime.h>
#include <math.h>

// Problem constants (fixed by setup_inputs)
#define NB    16
#define NH    76
#define NW    76
#define NCH   32          // 19 + NC
#define HW    (NH*NW)     // 5776
#define NL    21          // 2*NK + 3
#define TX    16
#define TY    8
#define TPB   (TX*TY)                    // 128
#define GXN   ((NW + TX - 1) / TX)       // 5
#define GYN   ((NH + TY - 1) / TY)       // 10
#define NBLK  (GXN * GYN * NB)           // 800
#define KSTR  56                         // s_key target-dim padding

#define FULLM 0xffffffffu
// Bias making every cull quantity strictly positive -> float order == uint order
#define KBIAS 1024.0f

__device__ float        g_partials[NBLK];
__device__ unsigned int g_count;   // zero at load; last block subtracts NBLK (replay-safe)

__device__ __forceinline__ float fsigmoid(float x) {
    return 1.0f / (1.0f + __expf(-x));
}

__global__ void __launch_bounds__(TPB)
loss_kernel(const float* __restrict__ out,
            const float* __restrict__ dst,
            const float* __restrict__ tgt,
            float* __restrict__ res)
{
    __shared__ uint4    s_key[9][KSTR];   // expanded box keys (biased-float bits), corner-major
    __shared__ unsigned s_mask[2];
    __shared__ int      s_map[TPB];       // packed (t+1)<<8 | cls for targeted cells
    __shared__ float    s_red[TPB / 32];
    __shared__ bool     s_last;

    const int b    = blockIdx.z;
    const int tid  = threadIdx.x;
    const int lane = tid & 31;
    const float* T = tgt + (size_t)b * (50 * NL);

    s_map[tid] = 0;

    // ---- Early: issue this thread's cell loads FIRST (hidden behind target prep) ----
    const int  bx0  = blockIdx.x * TX, by0 = blockIdx.y * TY;
    const int  i    = bx0 + (tid & (TX - 1));
    const int  j    = by0 + (tid >> 4);
    const bool inb  = (i < NW) && (j < NH);
    const int  cell = inb ? (j * NW + i) : 0;            // clamp: conservative box growth
    const float* O  = out + (size_t)b * NCH * HW + cell; // channel stride HW
    const float* D  = dst + (size_t)b * NCH * HW + cell;

    float ox[9], oy[9];
    #pragma unroll
    for (int k = 0; k < 9; k++) {
        ox[k] = O[(size_t)(2 * k    ) * HW];
        oy[k] = O[(size_t)(2 * k + 1) * HW];
    }
    float conf_raw  = O[(size_t)18 * HW];
    float tconf_raw = D[(size_t)18 * HW];

    // ---- Target prep: 450 corner-box tasks spread over all threads ----
    // key = bitcast(g*scale + (KBIAS -/+ 80.5)); all values positive -> uint order valid
    for (int task = tid; task < 450; task += TPB) {
        int t = task / 9, k = task - 9 * t;
        float rx = T[t * NL + 1 + 2 * k];
        float ry = T[t * NL + 2 + 2 * k];
        uint4 key;
        key.x = __float_as_uint(fmaf(rx, 640.0f, KBIAS - 80.5f));
        key.y = __float_as_uint(fmaf(rx, 640.0f, KBIAS + 80.5f));
        key.z = __float_as_uint(fmaf(ry, 480.0f, KBIAS - 80.5f));
        key.w = __float_as_uint(fmaf(ry, 480.0f, KBIAS + 80.5f));
        s_key[k][t] = key;
    }
    if (tid < 64) {   // warps 0,1 full — ballot legal
        float xv = (tid < 50) ? T[tid * NL + 1] : 0.0f;
        unsigned m = __ballot_sync(FULLM, xv != 0.0f);
        if (lane == 0) s_mask[tid >> 5] = m;
    }
    __syncthreads();

    // nv = leading-valid prefix length (cumprod semantics)
    const unsigned m0v = s_mask[0], m1v = s_mask[1];
    int nv;
    if (~m0v)      nv = __ffs(~m0v) - 1;
    else if (~m1v) nv = 32 + __ffs(~m1v) - 1;
    else           nv = 64;
    if (nv > 50) nv = 50;

    // Targeted-cell map (last valid t wins == max t wins)
    if (tid < nv) {
        int gi = (int)(T[tid * NL + 1] * (float)NW);
        int gj = (int)(T[tid * NL + 2] * (float)NH);
        int li = gi - bx0, lj = gj - by0;
        if (li >= 0 && li < TX && lj >= 0 && lj < TY)
            atomicMax(&s_map[lj * TX + li], ((tid + 1) << 8) | (int)T[tid * NL]);
    }
    __syncthreads();

    const float sX = 640.0f / (float)NW;
    const float sY = 480.0f / (float)NH;
    const float fi = (float)i, fj = (float)j;

    // Sigmoid only on corner 0 (loads long since arrived)
    ox[0] = fsigmoid(ox[0]);
    oy[0] = fsigmoid(oy[0]);

    // ---- Cell keys (biased-positive floats as uint), then batched REDUX ----
    unsigned kx[9], ky[9];
    #pragma unroll
    for (int k = 0; k < 9; k++) {
        kx[k] = __float_as_uint(fmaf(ox[k] + fi, sX, KBIAS));
        ky[k] = __float_as_uint(fmaf(oy[k] + fj, sY, KBIAS));
    }
    unsigned mnx[9], mxx[9], mny[9], mxy[9];
    #pragma unroll
    for (int k = 0; k < 9; k++) {
        mnx[k] = __reduce_min_sync(FULLM, kx[k]);
        mxx[k] = __reduce_max_sync(FULLM, kx[k]);
        mny[k] = __reduce_min_sync(FULLM, ky[k]);
        mxy[k] = __reduce_max_sync(FULLM, ky[k]);
    }

    // ---- Per-lane target cull: survivor iff >=6 corners overlap warp box ----
    int cnt0 = 0, cnt1 = 0;
    const bool nvgt32 = (nv > 32);
    #pragma unroll
    for (int k = 0; k < 9; k++) {
        uint4 tk = s_key[k][lane];
        cnt0 += (mnx[k] <= tk.y && mxx[k] >= tk.x &&
                 mny[k] <= tk.w && mxy[k] >= tk.z) ? 1 : 0;
    }
    if (nvgt32 && lane + 32 < 50) {
        #pragma unroll
        for (int k = 0; k < 9; k++) {
            uint4 tk = s_key[k][lane + 32];
            cnt1 += (mnx[k] <= tk.y && mxx[k] >= tk.x &&
                     mny[k] <= tk.w && mxy[k] >= tk.z) ? 1 : 0;
        }
    }
    unsigned sm0 = __ballot_sync(FULLM, (lane < nv) && cnt0 >= 6);
    unsigned sm1 = nvgt32 ? __ballot_sync(FULLM, (lane + 32 < nv) && cnt1 >= 6) : 0u;

    // ---- Exact evaluation for rare survivors (warp-uniform branch) ----
    bool sil = false;
    unsigned long long smask = (((unsigned long long)sm1) << 32) | sm0;
    if (smask) {
        float pcx[9], pcy[9];
        #pragma unroll
        for (int k = 0; k < 9; k++) {
            pcx[k] = (ox[k] + fi) * sX;
            pcy[k] = (oy[k] + fj) * sY;
        }
        do {
            int t = __ffsll(smask) - 1;
            smask &= smask - 1;
            const float* gp = T + t * NL;
            float d2[9];
            int cnt = 0;
            #pragma unroll
            for (int k = 0; k < 9; k++) {
                float gx = gp[1 + 2 * k] * 640.0f;
                float gy = gp[2 + 2 * k] * 480.0f;
                float dx = gx - pcx[k];
                float dy = gy - pcy[k];
                d2[k] = fmaf(dx, dx, dy * dy);
                cnt += (d2[k] < 6400.0f) ? 1 : 0;
            }
            if (cnt >= 6) {   // precise math; essentially never taken
                float s = 0.0f;
                #pragma unroll
                for (int k = 0; k < 9; k++) {
                    float dist = sqrtf(d2[k]);
                    float c = (expf(2.0f * (1.0f - dist * (1.0f / 80.0f))) - 1.0f)
                              * (1.0f / 6.3890560989306495f);   // 1/(e^2-1)
                    s += (dist < 80.0f) ? c : 0.0f;
                }
                if (s * (1.0f / 9.0f) > 0.6f) sil = true;
            }
        } while (smask);
    }

    // ---- Losses ----
    float loss = 0.0f;
    if (inb) {
        const float conf  = fsigmoid(conf_raw);
        const float tconf = fsigmoid(tconf_raw);
        const int   mpk      = s_map[tid];
        const bool  targeted = (mpk != 0);
        const int   tc       = mpk & 0xff;
        const float cm  = targeted ? 5.0f : (sil ? 0.0f : 1.0f);
        const float dcf = conf - tconf;
        loss = 0.5f * dcf * dcf * cm;

        if (targeted) {   // rare (~1 cell per target)
            float lc = 0.0f;
            {
                float d0 = ox[0] - fsigmoid(D[0]);      // ox[0] already sigmoided
                float d1 = oy[0] - fsigmoid(D[HW]);
                lc += d0 * d0 + d1 * d1;
            }
            #pragma unroll
            for (int k = 1; k < 9; k++) {
                float ddx = ox[k] - D[(size_t)(2 * k    ) * HW];
                float ddy = oy[k] - D[(size_t)(2 * k + 1) * HW];
                lc += ddx * ddx + ddy * ddy;
            }
            loss += 0.5f * lc;

            // class CE = logsumexp(logits) - logits[tcls]
            float l[13];
            #pragma unroll
            for (int c = 0; c < 13; c++) l[c] = O[(size_t)(19 + c) * HW];
            float mx = l[0];
            #pragma unroll
            for (int c = 1; c < 13; c++) mx = fmaxf(mx, l[c]);
            float se = 0.0f;
            #pragma unroll
            for (int c = 0; c < 13; c++) se += expf(l[c] - mx);
            loss += (mx + logf(se)) - l[tc];
        }
    }

    // Deterministic intra-block reduction (4 warps)
    #pragma unroll
    for (int off = 16; off; off >>= 1)
        loss += __shfl_down_sync(FULLM, loss, off);
    if (lane == 0) s_red[tid >> 5] = loss;
    __syncthreads();
    if (tid == 0) {
        float v = s_red[0] + s_red[1] + s_red[2] + s_red[3];
        g_partials[(blockIdx.z * GYN + blockIdx.y) * GXN + blockIdx.x] = v;
        __threadfence();
        unsigned old = atomicAdd(&g_count, 1u);
        s_last = (old == (unsigned)(NBLK - 1));
    }
    __syncthreads();

    // Last block: fixed-order final reduction (deterministic)
    if (s_last && tid < 32) {
        float s = 0.0f;
        for (int idx = tid; idx < NBLK; idx += 32)
            s += g_partials[idx];
        #pragma unroll
        for (int off = 16; off; off >>= 1)
            s += __shfl_down_sync(FULLM, s, off);
        if (tid == 0) {
            res[0] = s;
            atomicSub(&g_count, (unsigned)NBLK);   // replay-safe reset
        }
    }
}

extern "C" void kernel_launch(void* const* d_in, const int* in_sizes, int n_in,
                              void* d_out, int out_size)
{
    const float* out = (const float*)d_in[0];
    const float* dst = (const float*)d_in[1];
    const float* tgt = (const float*)d_in[2];
    (void)in_sizes; (void)n_in; (void)out_size;

    dim3 grid(GXN, GYN, NB);
    loss_kernel<<<grid, TPB>>>(out, dst, tgt, (float*)d_out);
}

// round 12
// speedup vs baseline: 1.3409x; 1.1604x over previous
#include <cuda_runtime.h>
#include <math.h>

// Problem constants (fixed by setup_inputs)
#define NB    16
#define NH    76
#define NW    76
#define NCH   32          // 19 + NC
#define HW    (NH*NW)     // 5776
#define NL    21          // 2*NK + 3
#define TX    16
#define TY    8
#define TPB   (TX*TY)                    // 128
#define GXN   ((NW + TX - 1) / TX)       // 5
#define GYN   ((NH + TY - 1) / TY)       // 10
#define NBLK  (GXN * GYN * NB)           // 800
#define KSTR  56                         // s_key target-dim padding

#define FULLM 0xffffffffu
// Bias making every cull quantity strictly positive -> float order == uint order
#define KBIAS 1024.0f

__device__ float        g_partials[NBLK];
__device__ unsigned int g_count;   // zero at load; last block subtracts NBLK (replay-safe)

__device__ __forceinline__ float fsigmoid(float x) {
    return 1.0f / (1.0f + __expf(-x));
}

__global__ void __launch_bounds__(TPB, 6)   // force regs<=85: 6 blocks/SM -> single wave
loss_kernel(const float* __restrict__ out,
            const float* __restrict__ dst,
            const float* __restrict__ tgt,
            float* __restrict__ res)
{
    __shared__ uint4    s_key[9][KSTR];   // expanded box keys (biased-float bits), corner-major
    __shared__ unsigned s_mask[2];
    __shared__ int      s_map[TPB];       // packed (t+1)<<8 | cls for targeted cells
    __shared__ float    s_red[TPB / 32];
    __shared__ bool     s_last;

    const int b    = blockIdx.z;
    const int tid  = threadIdx.x;
    const int lane = tid & 31;
    const float* T = tgt + (size_t)b * (50 * NL);

    s_map[tid] = 0;

    // Phase 1: 450 corner-box key tasks spread over all threads
    // key = bitcast(g*scale + (KBIAS -/+ 80.5)); positive values -> uint order valid
    for (int task = tid; task < 450; task += TPB) {
        int t = task / 9, k = task - 9 * t;
        float rx = T[t * NL + 1 + 2 * k];
        float ry = T[t * NL + 2 + 2 * k];
        uint4 key;
        key.x = __float_as_uint(fmaf(rx, 640.0f, KBIAS - 80.5f));
        key.y = __float_as_uint(fmaf(rx, 640.0f, KBIAS + 80.5f));
        key.z = __float_as_uint(fmaf(ry, 480.0f, KBIAS - 80.5f));
        key.w = __float_as_uint(fmaf(ry, 480.0f, KBIAS + 80.5f));
        s_key[k][t] = key;
    }
    if (tid < 64) {   // warps 0,1 full — ballot legal
        float xv = (tid < 50) ? T[tid * NL + 1] : 0.0f;
        unsigned m = __ballot_sync(FULLM, xv != 0.0f);
        if (lane == 0) s_mask[tid >> 5] = m;
    }
    __syncthreads();

    // nv = leading-valid prefix length (cumprod semantics)
    const unsigned m0v = s_mask[0], m1v = s_mask[1];
    int nv;
    if (~m0v)      nv = __ffs(~m0v) - 1;
    else if (~m1v) nv = 32 + __ffs(~m1v) - 1;
    else           nv = 64;
    if (nv > 50) nv = 50;

    // Phase 2: targeted-cell map (last valid t wins == max t wins)
    const int bx0 = blockIdx.x * TX, by0 = blockIdx.y * TY;
    if (tid < nv) {
        int gi = (int)(T[tid * NL + 1] * (float)NW);
        int gj = (int)(T[tid * NL + 2] * (float)NH);
        int li = gi - bx0, lj = gj - by0;
        if (li >= 0 && li < TX && lj >= 0 && lj < TY)
            atomicMax(&s_map[lj * TX + li], ((tid + 1) << 8) | (int)T[tid * NL]);
    }
    __syncthreads();

    const int  i    = bx0 + (tid & (TX - 1));
    const int  j    = by0 + (tid >> 4);
    const bool inb  = (i < NW) && (j < NH);
    const int  cell = inb ? (j * NW + i) : 0;            // clamp: conservative box growth
    const float* O  = out + (size_t)b * NCH * HW + cell; // channel stride HW
    const float* D  = dst + (size_t)b * NCH * HW + cell;

    const float sX = 640.0f / (float)NW;
    const float sY = 480.0f / (float)NH;
    const float fi = (float)i, fj = (float)j;

    bool sil = false;
    float conf_raw = 0.0f, tconf_raw = 0.0f;
    float ox[9], oy[9];

    const unsigned actm = __ballot_sync(FULLM, inb);
    if (actm) {   // warp-uniform: skip fully out-of-range warps
        // Loads issued here (post-sync, naturally staggered across CTAs)
        #pragma unroll
        for (int k = 0; k < 9; k++) {
            ox[k] = O[(size_t)(2 * k    ) * HW];
            oy[k] = O[(size_t)(2 * k + 1) * HW];
        }
        conf_raw  = O[(size_t)18 * HW];
        tconf_raw = D[(size_t)18 * HW];
        ox[0] = fsigmoid(ox[0]);
        oy[0] = fsigmoid(oy[0]);

        // Cell keys (biased-positive floats as uint), then 36 independent REDUX batched
        unsigned kx[9], ky[9];
        #pragma unroll
        for (int k = 0; k < 9; k++) {
            kx[k] = __float_as_uint(fmaf(ox[k] + fi, sX, KBIAS));
            ky[k] = __float_as_uint(fmaf(oy[k] + fj, sY, KBIAS));
        }
        unsigned mnx[9], mxx[9], mny[9], mxy[9];
        #pragma unroll
        for (int k = 0; k < 9; k++) {
            mnx[k] = __reduce_min_sync(FULLM, kx[k]);
            mxx[k] = __reduce_max_sync(FULLM, kx[k]);
            mny[k] = __reduce_min_sync(FULLM, ky[k]);
            mxy[k] = __reduce_max_sync(FULLM, ky[k]);
        }

        // Per-lane target cull: survivor iff >=6 corners overlap warp box
        int cnt0 = 0, cnt1 = 0;
        const bool nvgt32 = (nv > 32);
        #pragma unroll
        for (int k = 0; k < 9; k++) {
            uint4 tk = s_key[k][lane];
            cnt0 += (mnx[k] <= tk.y && mxx[k] >= tk.x &&
                     mny[k] <= tk.w && mxy[k] >= tk.z) ? 1 : 0;
        }
        if (nvgt32 && lane + 32 < 50) {
            #pragma unroll
            for (int k = 0; k < 9; k++) {
                uint4 tk = s_key[k][lane + 32];
                cnt1 += (mnx[k] <= tk.y && mxx[k] >= tk.x &&
                         mny[k] <= tk.w && mxy[k] >= tk.z) ? 1 : 0;
            }
        }
        unsigned sm0 = __ballot_sync(FULLM, (lane < nv) && cnt0 >= 6);
        unsigned sm1 = nvgt32 ? __ballot_sync(FULLM, (lane + 32 < nv) && cnt1 >= 6) : 0u;

        // Exact evaluation for rare survivors (warp-uniform branch)
        unsigned long long smask = (((unsigned long long)sm1) << 32) | sm0;
        if (smask) {
            float pcx[9], pcy[9];
            #pragma unroll
            for (int k = 0; k < 9; k++) {
                pcx[k] = (ox[k] + fi) * sX;
                pcy[k] = (oy[k] + fj) * sY;
            }
            do {
                int t = __ffsll(smask) - 1;
                smask &= smask - 1;
                const float* gp = T + t * NL;
                float d2[9];
                int cnt = 0;
                #pragma unroll
                for (int k = 0; k < 9; k++) {
                    float gx = gp[1 + 2 * k] * 640.0f;
                    float gy = gp[2 + 2 * k] * 480.0f;
                    float dx = gx - pcx[k];
                    float dy = gy - pcy[k];
                    d2[k] = fmaf(dx, dx, dy * dy);
                    cnt += (d2[k] < 6400.0f) ? 1 : 0;
                }
                if (cnt >= 6) {   // precise math; essentially never taken
                    float s = 0.0f;
                    #pragma unroll
                    for (int k = 0; k < 9; k++) {
                        float dist = sqrtf(d2[k]);
                        float c = (expf(2.0f * (1.0f - dist * (1.0f / 80.0f))) - 1.0f)
                                  * (1.0f / 6.3890560989306495f);   // 1/(e^2-1)
                        s += (dist < 80.0f) ? c : 0.0f;
                    }
                    if (s * (1.0f / 9.0f) > 0.6f) sil = true;
                }
            } while (smask);
        }
    }

    // Losses
    float loss = 0.0f;
    if (inb) {
        const float conf  = fsigmoid(conf_raw);
        const float tconf = fsigmoid(tconf_raw);
        const int   mpk      = s_map[tid];
        const bool  targeted = (mpk != 0);
        const int   tc       = mpk & 0xff;
        const float cm  = targeted ? 5.0f : (sil ? 0.0f : 1.0f);
        const float dcf = conf - tconf;
        loss = 0.5f * dcf * dcf * cm;

        if (targeted) {   // rare (~1 cell per target)
            float lc = 0.0f;
            {
                float d0 = ox[0] - fsigmoid(D[0]);      // ox[0] already sigmoided
                float d1 = oy[0] - fsigmoid(D[HW]);
                lc += d0 * d0 + d1 * d1;
            }
            #pragma unroll
            for (int k = 1; k < 9; k++) {
                float ddx = ox[k] - D[(size_t)(2 * k    ) * HW];
                float ddy = oy[k] - D[(size_t)(2 * k + 1) * HW];
                lc += ddx * ddx + ddy * ddy;
            }
            loss += 0.5f * lc;

            // class CE = logsumexp(logits) - logits[tcls]
            float l[13];
            #pragma unroll
            for (int c = 0; c < 13; c++) l[c] = O[(size_t)(19 + c) * HW];
            float mx = l[0];
            #pragma unroll
            for (int c = 1; c < 13; c++) mx = fmaxf(mx, l[c]);
            float se = 0.0f;
            #pragma unroll
            for (int c = 0; c < 13; c++) se += expf(l[c] - mx);
            loss += (mx + logf(se)) - l[tc];
        }
    }

    // Deterministic intra-block reduction (4 warps)
    #pragma unroll
    for (int off = 16; off; off >>= 1)
        loss += __shfl_down_sync(FULLM, loss, off);
    if (lane == 0) s_red[tid >> 5] = loss;
    __syncthreads();
    if (tid == 0) {
        float v = s_red[0] + s_red[1] + s_red[2] + s_red[3];
        g_partials[(blockIdx.z * GYN + blockIdx.y) * GXN + blockIdx.x] = v;
        __threadfence();
        unsigned old = atomicAdd(&g_count, 1u);
        s_last = (old == (unsigned)(NBLK - 1));
    }
    __syncthreads();

    // Last block: fixed-order final reduction (deterministic)
    if (s_last && tid < 32) {
        float s = 0.0f;
        for (int idx = tid; idx < NBLK; idx += 32)
            s += g_partials[idx];
        #pragma unroll
        for (int off = 16; off; off >>= 1)
            s += __shfl_down_sync(FULLM, s, off);
        if (tid == 0) {
            res[0] = s;
            atomicSub(&g_count, (unsigned)NBLK);   // replay-safe reset
        }
    }
}

extern "C" void kernel_launch(void* const* d_in, const int* in_sizes, int n_in,
                              void* d_out, int out_size)
{
    const float* out = (const float*)d_in[0];
    const float* dst = (const float*)d_in[1];
    const float* tgt = (const float*)d_in[2];
    (void)in_sizes; (void)n_in; (void)out_size;

    dim3 grid(GXN, GYN, NB);
    loss_kernel<<<grid, TPB>>>(out, dst, tgt, (float*)d_out);
}